// round 10
// baseline (speedup 1.0000x reference)
#include <cuda_runtime.h>
#include <cuda_bf16.h>
#include <math.h>
#include <stdint.h>

#define NN    50000
#define DH    256
#define DOUT  128
#define EMAX  800000

// ---------------- scratch (device globals; referenced by symbol only) --------
__device__ float g_h   [(size_t)NN * DH];        // GEMM output (fp32)
__device__ __nv_bfloat16 g_ah[(size_t)NN * DH];  // A split hi (GEMM input)
__device__ __nv_bfloat16 g_al[(size_t)NN * DH];  // A split lo
__device__ __nv_bfloat16 g_wth[2 * 65536 + 32768]; // W^T hi (3 layers, [m][k])
__device__ __nv_bfloat16 g_wtl[2 * 65536 + 32768]; // W^T lo
__device__ float g_dinv[NN];
__device__ int   g_cnt [NN];
__device__ int   g_rowptr[NN + 1];
__device__ int   g_cursor[NN];
__device__ int   g_csr_src[EMAX];
__device__ float g_csr_w  [EMAX];
__device__ int   g_is64;

__device__ __forceinline__ uint32_t smem_u32(const void* p) {
    uint32_t a;
    asm("{ .reg .u64 t; cvta.to.shared.u64 t, %1; cvt.u32.u64 %0, t; }"
        : "=r"(a) : "l"(p));
    return a;
}

// ---------------- hi/lo split --------------------------------------------------
__device__ __forceinline__ void split1(float v, unsigned short& hb, unsigned short& lb) {
    __nv_bfloat16 h = __float2bfloat16(v);
    float hf = __bfloat162float(h);
    __nv_bfloat16 l = __float2bfloat16(v - hf);
    hb = reinterpret_cast<unsigned short&>(h);
    lb = reinterpret_cast<unsigned short&>(l);
}

// ---------------- fused edge-independent prep ---------------------------------
// one launch: weight transpose+split (3 layers), x split, cnt zero, dtype probe
__global__ void k_prep0(const float* __restrict__ W1,
                        const float* __restrict__ W2,
                        const float* __restrict__ W3,
                        const float* __restrict__ x,
                        const int*   __restrict__ ei32, int n4) {
    int i = blockIdx.x * blockDim.x + threadIdx.x;

    // x split: fp32 -> hi/lo bf16 (i over N*DH/4 float4s)
    if (i < n4) {
        float4 v = ((const float4*)x)[i];
        ushort4 hv, lv;
        split1(v.x, hv.x, lv.x);
        split1(v.y, hv.y, lv.y);
        split1(v.z, hv.z, lv.z);
        split1(v.w, hv.w, lv.w);
        ((ushort4*)g_ah)[i] = hv;
        ((ushort4*)g_al)[i] = lv;
    }
    // weights
    if (i < 163840) {
        const float* W; int M, off, j = i;
        if (j < 65536)       { W = W1; M = DH;   off = 0;      }
        else if (j < 131072) { W = W2; M = DH;   off = 65536;  j -= 65536;  }
        else                 { W = W3; M = DOUT; off = 131072; j -= 131072; }
        int k = j / M, m = j % M;
        unsigned short hb, lb;
        split1(W[j], hb, lb);
        g_wth[off + (size_t)m * DH + k] = reinterpret_cast<__nv_bfloat16&>(hb);
        g_wtl[off + (size_t)m * DH + k] = reinterpret_cast<__nv_bfloat16&>(lb);
    }
    // zero degree counters
    if (i < NN) g_cnt[i] = 0;
    // dtype probe
    if (blockIdx.x == 0) {
        __shared__ int any;
        if (threadIdx.x == 0) any = 0;
        __syncthreads();
        int a = 0;
        for (int k = threadIdx.x; k < 1024; k += blockDim.x)
            if (ei32[2 * k + 1] != 0) a = 1;
        if (a) atomicOr(&any, 1);
        __syncthreads();
        if (threadIdx.x == 0) g_is64 = any ? 0 : 1;
    }
}

__device__ __forceinline__ int ld_idx(const void* ei, size_t pos) {
    int v;
    if (g_is64) v = (int)((const long long*)ei)[pos];
    else        v = ((const int*)ei)[pos];
    return min(max(v, 0), NN - 1);
}

__global__ void k_cnt_acc(const void* __restrict__ ei, int E) {
    int e = blockIdx.x * blockDim.x + threadIdx.x;
    if (e < E) atomicAdd(&g_cnt[ld_idx(ei, (size_t)E + e)], 1);
}

// exclusive scan over g_cnt (single block) + dinv
__global__ void k_scan() {
    const int T = 1024;
    __shared__ int part[T];
    int tid = threadIdx.x;
    int chunk = (NN + T - 1) / T;
    int base = tid * chunk;
    int sum = 0;
    for (int i = 0; i < chunk; i++) {
        int j = base + i;
        if (j < NN) {
            int c = g_cnt[j];
            sum += c;
            g_dinv[j] = rsqrtf(1.0f + (float)c);
        }
    }
    part[tid] = sum;
    __syncthreads();
    for (int off = 1; off < T; off <<= 1) {
        int v = (tid >= off) ? part[tid - off] : 0;
        __syncthreads();
        part[tid] += v;
        __syncthreads();
    }
    int run = (tid > 0) ? part[tid - 1] : 0;
    for (int i = 0; i < chunk; i++) {
        int j = base + i;
        if (j < NN) {
            int c = g_cnt[j];
            g_rowptr[j] = run;
            g_cursor[j] = run;
            run += c;
        }
    }
    if (tid == T - 1) g_rowptr[NN] = run;
}

// CSR fill with fused norm computation (reads ei + dinv directly)
__global__ void k_fill(const void* __restrict__ ei, int E) {
    int e = blockIdx.x * blockDim.x + threadIdx.x;
    if (e < E) {
        int s = ld_idx(ei, (size_t)e);
        int d = ld_idx(ei, (size_t)E + e);
        int pos = atomicAdd(&g_cursor[d], 1);
        g_csr_src[pos] = s;
        g_csr_w  [pos] = g_dinv[s] * g_dinv[d];
    }
}

// ---------------- mma.sync bf16 split GEMM with cp.async double buffer ---------
#define SSTR 40
#define BUFSH 20480                 // shorts per buffer (4 arrays x 5120)

__device__ __forceinline__ void ldsm_x4(uint32_t& r0, uint32_t& r1,
                                        uint32_t& r2, uint32_t& r3, uint32_t a) {
    asm volatile("ldmatrix.sync.aligned.m8n8.x4.shared.b16 {%0,%1,%2,%3}, [%4];"
                 : "=r"(r0), "=r"(r1), "=r"(r2), "=r"(r3) : "r"(a));
}
__device__ __forceinline__ void ldsm_x2(uint32_t& r0, uint32_t& r1, uint32_t a) {
    asm volatile("ldmatrix.sync.aligned.m8n8.x2.shared.b16 {%0,%1}, [%2];"
                 : "=r"(r0), "=r"(r1) : "r"(a));
}
__device__ __forceinline__ void mma16816(float* d, const uint32_t* a, const uint32_t* b) {
    asm volatile(
        "mma.sync.aligned.m16n8k16.row.col.f32.bf16.bf16.f32 "
        "{%0,%1,%2,%3}, {%4,%5,%6,%7}, {%8,%9}, {%0,%1,%2,%3};"
        : "+f"(d[0]), "+f"(d[1]), "+f"(d[2]), "+f"(d[3])
        : "r"(a[0]), "r"(a[1]), "r"(a[2]), "r"(a[3]), "r"(b[0]), "r"(b[1]));
}
__device__ __forceinline__ void cp16(uint32_t d, const void* s, int sz) {
    asm volatile("cp.async.cg.shared.global [%0], [%1], 16, %2;"
                 :: "r"(d), "l"(s), "r"(sz));
}

__global__ __launch_bounds__(256) void k_mgemm(int N, int M, int woff) {
    extern __shared__ __align__(16) unsigned short smem[];

    const int tid = threadIdx.x;
    const int wid = tid >> 5;
    const int lane = tid & 31;
    const int wm = wid >> 2;
    const int wn = wid & 3;
    const int row0 = blockIdx.x * 128;
    const int col0 = blockIdx.y * 128;

    float acc[4][4][4];
    #pragma unroll
    for (int i = 0; i < 4; i++)
        #pragma unroll
        for (int j = 0; j < 4; j++)
            #pragma unroll
            for (int q = 0; q < 4; q++) acc[i][j][q] = 0.f;

    const uint32_t sbase = smem_u32(smem);

    auto stage = [&](int buf, int k0) {
        uint32_t b0 = sbase + (uint32_t)buf * (BUFSH * 2);
        #pragma unroll
        for (int l = 0; l < 2; l++) {
            int idx = tid + l * 256;
            int r = idx >> 2, v = idx & 3;
            uint32_t d = b0 + (uint32_t)(r * SSTR + v * 8) * 2;
            int row = row0 + r;
            int sz = (row < N) ? 16 : 0;
            size_t ga = (size_t)row * DH + k0 + v * 8;
            cp16(d,             &g_ah[ga], sz);
            cp16(d + 5120 * 2,  &g_al[ga], sz);
            size_t gb = (size_t)woff + (size_t)(col0 + r) * DH + k0 + v * 8;
            cp16(d + 10240 * 2, &g_wth[gb], 16);
            cp16(d + 15360 * 2, &g_wtl[gb], 16);
        }
        asm volatile("cp.async.commit_group;");
    };

    stage(0, 0);

    for (int c = 0; c < 8; c++) {
        int buf = c & 1;
        if (c < 7) {
            stage(buf ^ 1, (c + 1) * 32);
            asm volatile("cp.async.wait_group 1;");
        } else {
            asm volatile("cp.async.wait_group 0;");
        }
        __syncthreads();

        uint32_t bAh = sbase + (uint32_t)buf * (BUFSH * 2);
        uint32_t bAl = bAh + 5120 * 2;
        uint32_t bBh = bAh + 10240 * 2;
        uint32_t bBl = bAh + 15360 * 2;

        #pragma unroll
        for (int kk = 0; kk < 32; kk += 16) {
            uint32_t ah[4][4], al[4][4];
            #pragma unroll
            for (int tm = 0; tm < 4; tm++) {
                int r = wm * 64 + tm * 16 + (lane & 15);
                uint32_t off = (uint32_t)(r * SSTR + kk + (lane >> 4) * 8) * 2;
                ldsm_x4(ah[tm][0], ah[tm][1], ah[tm][2], ah[tm][3], bAh + off);
                ldsm_x4(al[tm][0], al[tm][1], al[tm][2], al[tm][3], bAl + off);
            }
            #pragma unroll
            for (int tn = 0; tn < 4; tn++) {
                int r = wn * 32 + tn * 8 + (lane & 7);
                uint32_t off = (uint32_t)(r * SSTR + kk + ((lane >> 3) & 1) * 8) * 2;
                uint32_t bh[2], bl[2];
                ldsm_x2(bh[0], bh[1], bBh + off);
                ldsm_x2(bl[0], bl[1], bBl + off);
                #pragma unroll
                for (int tm = 0; tm < 4; tm++) {
                    mma16816(acc[tm][tn], ah[tm], bh);
                    mma16816(acc[tm][tn], al[tm], bh);
                    mma16816(acc[tm][tn], ah[tm], bl);
                }
            }
        }
        __syncthreads();
    }

    #pragma unroll
    for (int tm = 0; tm < 4; tm++) {
        int r0r = row0 + wm * 64 + tm * 16 + (lane >> 2);
        #pragma unroll
        for (int tn = 0; tn < 4; tn++) {
            int col = col0 + wn * 32 + tn * 8 + (lane & 3) * 2;
            if (r0r < N)
                *(float2*)&g_h[(size_t)r0r * M + col] =
                    make_float2(acc[tm][tn][0], acc[tm][tn][1]);
            if (r0r + 8 < N)
                *(float2*)&g_h[(size_t)(r0r + 8) * M + col] =
                    make_float2(acc[tm][tn][2], acc[tm][tn][3]);
        }
    }
}

// ---------------- aggregation (gather) + fused relu/split --------------------
__global__ void k_agg(const float* __restrict__ b, float* __restrict__ oext,
                      int M, int mode)
{
    int node = blockIdx.x;
    int c    = threadIdx.x;

    float di = g_dinv[node];
    float s  = di * di;
    float4 hv = *(const float4*)&g_h[(size_t)node * M + c * 4];
    float4 bv = *(const float4*)&b[c * 4];
    float4 acc;
    acc.x = fmaf(hv.x, s, bv.x);
    acc.y = fmaf(hv.y, s, bv.y);
    acc.z = fmaf(hv.z, s, bv.z);
    acc.w = fmaf(hv.w, s, bv.w);

    int e   = g_rowptr[node];
    int end = g_rowptr[node + 1];

    for (; e + 3 < end; e += 4) {
        int   s0 = g_csr_src[e],     s1 = g_csr_src[e + 1];
        int   s2 = g_csr_src[e + 2], s3 = g_csr_src[e + 3];
        float w0 = g_csr_w[e],     w1 = g_csr_w[e + 1];
        float w2 = g_csr_w[e + 2], w3 = g_csr_w[e + 3];
        float4 v0 = *(const float4*)&g_h[(size_t)s0 * M + c * 4];
        float4 v1 = *(const float4*)&g_h[(size_t)s1 * M + c * 4];
        float4 v2 = *(const float4*)&g_h[(size_t)s2 * M + c * 4];
        float4 v3 = *(const float4*)&g_h[(size_t)s3 * M + c * 4];
        acc.x = fmaf(v0.x, w0, acc.x); acc.y = fmaf(v0.y, w0, acc.y);
        acc.z = fmaf(v0.z, w0, acc.z); acc.w = fmaf(v0.w, w0, acc.w);
        acc.x = fmaf(v1.x, w1, acc.x); acc.y = fmaf(v1.y, w1, acc.y);
        acc.z = fmaf(v1.z, w1, acc.z); acc.w = fmaf(v1.w, w1, acc.w);
        acc.x = fmaf(v2.x, w2, acc.x); acc.y = fmaf(v2.y, w2, acc.y);
        acc.z = fmaf(v2.z, w2, acc.z); acc.w = fmaf(v2.w, w2, acc.w);
        acc.x = fmaf(v3.x, w3, acc.x); acc.y = fmaf(v3.y, w3, acc.y);
        acc.z = fmaf(v3.z, w3, acc.z); acc.w = fmaf(v3.w, w3, acc.w);
    }
    for (; e < end; e++) {
        int   s0 = g_csr_src[e];
        float w0 = g_csr_w[e];
        float4 v0 = *(const float4*)&g_h[(size_t)s0 * M + c * 4];
        acc.x = fmaf(v0.x, w0, acc.x); acc.y = fmaf(v0.y, w0, acc.y);
        acc.z = fmaf(v0.z, w0, acc.z); acc.w = fmaf(v0.w, w0, acc.w);
    }

    if (mode == 0) {
        acc.x = fmaxf(acc.x, 0.f); acc.y = fmaxf(acc.y, 0.f);
        acc.z = fmaxf(acc.z, 0.f); acc.w = fmaxf(acc.w, 0.f);
        ushort4 hvs, lvs;
        split1(acc.x, hvs.x, lvs.x);
        split1(acc.y, hvs.y, lvs.y);
        split1(acc.z, hvs.z, lvs.z);
        split1(acc.w, hvs.w, lvs.w);
        size_t o = ((size_t)node * M) / 4 + c;
        ((ushort4*)g_ah)[o] = hvs;
        ((ushort4*)g_al)[o] = lvs;
    } else {
        *(float4*)&oext[(size_t)node * M + c * 4] = acc;
    }
}

// ---------------- launch -----------------------------------------------------
extern "C" void kernel_launch(void* const* d_in, const int* in_sizes, int n_in,
                              void* d_out, int out_size)
{
    const float* x  = (const float*)d_in[0];
    const void*  ei = d_in[1];
    const float* W1 = (const float*)d_in[2];
    const float* b1 = (const float*)d_in[3];
    const float* W2 = (const float*)d_in[4];
    const float* b2 = (const float*)d_in[5];
    const float* W3 = (const float*)d_in[6];
    const float* b3 = (const float*)d_in[7];
    float* out = (float*)d_out;

    const int N = NN;
    const int E = in_sizes[1] / 2;
    const int n4 = N * (DH / 4);
    const int SM_BYTES = 2 * BUFSH * 2;   // 81920

    // idempotent, capture-safe, no static state
    cudaFuncSetAttribute(k_mgemm, cudaFuncAttributeMaxDynamicSharedMemorySize,
                         SM_BYTES);

    dim3 tg_h((N + 127) / 128, DH / 128);    // 391 x 2
    dim3 tg_o((N + 127) / 128, DOUT / 128);  // 391 x 1

    k_prep0  <<<(n4 + 255) / 256, 256>>>(W1, W2, W3, x, (const int*)ei, n4); // 0
    k_cnt_acc<<<(E + 255) / 256, 256>>>(ei, E);                              // 1
    k_scan   <<<1, 1024>>>();                                                // 2
    k_fill   <<<(E + 255) / 256, 256>>>(ei, E);                              // 3

    k_mgemm  <<<tg_h, 256, SM_BYTES>>>(N, DH, 0);                            // 4
    k_agg    <<<N, DH / 4>>>(b1, out, DH, 0);                                // 5

    k_mgemm  <<<tg_h, 256, SM_BYTES>>>(N, DH, 65536);                        // 6
    k_agg    <<<N, DH / 4>>>(b2, out, DH, 0);                                // 7

    k_mgemm  <<<tg_o, 256, SM_BYTES>>>(N, DOUT, 131072);                     // 8
    k_agg    <<<N, DOUT / 4>>>(b3, out, DOUT, 1);                            // 9
}

// round 11
// speedup vs baseline: 1.0433x; 1.0433x over previous
#include <cuda_runtime.h>
#include <cuda_bf16.h>
#include <cuda_fp16.h>
#include <math.h>
#include <stdint.h>

#define NN    50000
#define DH    256
#define DOUT  128
#define EMAX  800000

// ---------------- scratch (device globals; referenced by symbol only) --------
__device__ __half g_h  [(size_t)NN * DH];        // GEMM output (fp16)
__device__ __nv_bfloat16 g_ah[(size_t)NN * DH];  // A split hi (GEMM input)
__device__ __nv_bfloat16 g_al[(size_t)NN * DH];  // A split lo
__device__ __nv_bfloat16 g_wth[2 * 65536 + 32768]; // W^T hi (3 layers, [m][k])
__device__ __nv_bfloat16 g_wtl[2 * 65536 + 32768]; // W^T lo
__device__ float g_dinv[NN];
__device__ int   g_cnt [NN];                     // zero-init; re-zeroed by k_scan
__device__ int   g_rowptr[NN + 1];
__device__ int   g_cursor[NN];
__device__ int   g_csr_src[EMAX];
__device__ float g_csr_w  [EMAX];
__device__ int   g_is64;

__device__ __forceinline__ uint32_t smem_u32(const void* p) {
    uint32_t a;
    asm("{ .reg .u64 t; cvta.to.shared.u64 t, %1; cvt.u32.u64 %0, t; }"
        : "=r"(a) : "l"(p));
    return a;
}

// ---------------- hi/lo split --------------------------------------------------
__device__ __forceinline__ void split1(float v, unsigned short& hb, unsigned short& lb) {
    __nv_bfloat16 h = __float2bfloat16(v);
    float hf = __bfloat162float(h);
    __nv_bfloat16 l = __float2bfloat16(v - hf);
    hb = reinterpret_cast<unsigned short&>(h);
    lb = reinterpret_cast<unsigned short&>(l);
}

__device__ __forceinline__ int clampi(int v) { return min(max(v, 0), NN - 1); }

// ---------------- fused edge-independent prep ---------------------------------
// one launch: weight split, x split, dtype probe (per-block), degree count
__global__ void k_prep0(const float* __restrict__ W1,
                        const float* __restrict__ W2,
                        const float* __restrict__ W3,
                        const float* __restrict__ x,
                        const void* __restrict__ ei, int n4, int E) {
    int i = blockIdx.x * blockDim.x + threadIdx.x;

    // per-block dtype probe (int64 node ids < 50000 -> odd int32 words all 0)
    __shared__ int s_any;
    if (threadIdx.x == 0) s_any = 0;
    __syncthreads();
    {
        const int* ei32 = (const int*)ei;
        int a = 0;
        for (int k = threadIdx.x; k < 1024; k += blockDim.x)
            if (ei32[2 * k + 1] != 0) a = 1;
        if (a) atomicOr(&s_any, 1);
    }
    __syncthreads();
    const int is64 = s_any ? 0 : 1;
    if (i == 0) g_is64 = is64;

    // x split: fp32 -> hi/lo bf16
    if (i < n4) {
        float4 v = ((const float4*)x)[i];
        ushort4 hv, lv;
        split1(v.x, hv.x, lv.x);
        split1(v.y, hv.y, lv.y);
        split1(v.z, hv.z, lv.z);
        split1(v.w, hv.w, lv.w);
        ((ushort4*)g_ah)[i] = hv;
        ((ushort4*)g_al)[i] = lv;
    }
    // weights
    if (i < 163840) {
        const float* W; int M, off, j = i;
        if (j < 65536)       { W = W1; M = DH;   off = 0;      }
        else if (j < 131072) { W = W2; M = DH;   off = 65536;  j -= 65536;  }
        else                 { W = W3; M = DOUT; off = 131072; j -= 131072; }
        int k = j / M, m = j % M;
        unsigned short hb, lb;
        split1(W[j], hb, lb);
        g_wth[off + (size_t)m * DH + k] = reinterpret_cast<__nv_bfloat16&>(hb);
        g_wtl[off + (size_t)m * DH + k] = reinterpret_cast<__nv_bfloat16&>(lb);
    }
    // degree count (g_cnt zeroed by previous run's k_scan / static init)
    if (i < E) {
        int d;
        if (is64) d = (int)((const long long*)ei)[(size_t)E + i];
        else      d = ((const int*)ei)[(size_t)E + i];
        atomicAdd(&g_cnt[clampi(d)], 1);
    }
}

__device__ __forceinline__ int ld_idx(const void* ei, size_t pos) {
    int v;
    if (g_is64) v = (int)((const long long*)ei)[pos];
    else        v = ((const int*)ei)[pos];
    return clampi(v);
}

// exclusive scan over g_cnt (single block) + dinv + re-zero cnt for next replay
__global__ void k_scan() {
    const int T = 1024;
    __shared__ int part[T];
    int tid = threadIdx.x;
    int chunk = (NN + T - 1) / T;
    int base = tid * chunk;
    int sum = 0;
    for (int i = 0; i < chunk; i++) {
        int j = base + i;
        if (j < NN) {
            int c = g_cnt[j];
            sum += c;
            g_dinv[j] = rsqrtf(1.0f + (float)c);
        }
    }
    part[tid] = sum;
    __syncthreads();
    for (int off = 1; off < T; off <<= 1) {
        int v = (tid >= off) ? part[tid - off] : 0;
        __syncthreads();
        part[tid] += v;
        __syncthreads();
    }
    int run = (tid > 0) ? part[tid - 1] : 0;
    for (int i = 0; i < chunk; i++) {
        int j = base + i;
        if (j < NN) {
            int c = g_cnt[j];
            g_rowptr[j] = run;
            g_cursor[j] = run;
            g_cnt[j]    = 0;      // clean for next graph replay
            run += c;
        }
    }
    if (tid == T - 1) g_rowptr[NN] = run;
}

// CSR fill with fused norm computation
__global__ void k_fill(const void* __restrict__ ei, int E) {
    int e = blockIdx.x * blockDim.x + threadIdx.x;
    if (e < E) {
        int s = ld_idx(ei, (size_t)e);
        int d = ld_idx(ei, (size_t)E + e);
        int pos = atomicAdd(&g_cursor[d], 1);
        g_csr_src[pos] = s;
        g_csr_w  [pos] = g_dinv[s] * g_dinv[d];
    }
}

// ---------------- mma.sync bf16 split GEMM with cp.async double buffer ---------
#define SSTR 40
#define BUFSH 20480                 // shorts per buffer (4 arrays x 5120)

__device__ __forceinline__ void ldsm_x4(uint32_t& r0, uint32_t& r1,
                                        uint32_t& r2, uint32_t& r3, uint32_t a) {
    asm volatile("ldmatrix.sync.aligned.m8n8.x4.shared.b16 {%0,%1,%2,%3}, [%4];"
                 : "=r"(r0), "=r"(r1), "=r"(r2), "=r"(r3) : "r"(a));
}
__device__ __forceinline__ void ldsm_x2(uint32_t& r0, uint32_t& r1, uint32_t a) {
    asm volatile("ldmatrix.sync.aligned.m8n8.x2.shared.b16 {%0,%1}, [%2];"
                 : "=r"(r0), "=r"(r1) : "r"(a));
}
__device__ __forceinline__ void mma16816(float* d, const uint32_t* a, const uint32_t* b) {
    asm volatile(
        "mma.sync.aligned.m16n8k16.row.col.f32.bf16.bf16.f32 "
        "{%0,%1,%2,%3}, {%4,%5,%6,%7}, {%8,%9}, {%0,%1,%2,%3};"
        : "+f"(d[0]), "+f"(d[1]), "+f"(d[2]), "+f"(d[3])
        : "r"(a[0]), "r"(a[1]), "r"(a[2]), "r"(a[3]), "r"(b[0]), "r"(b[1]));
}
__device__ __forceinline__ void cp16(uint32_t d, const void* s, int sz) {
    asm volatile("cp.async.cg.shared.global [%0], [%1], 16, %2;"
                 :: "r"(d), "l"(s), "r"(sz));
}

__global__ __launch_bounds__(256) void k_mgemm(int N, int M, int woff) {
    extern __shared__ __align__(16) unsigned short smem[];

    const int tid = threadIdx.x;
    const int wid = tid >> 5;
    const int lane = tid & 31;
    const int wm = wid >> 2;
    const int wn = wid & 3;
    const int row0 = blockIdx.x * 128;
    const int col0 = blockIdx.y * 128;

    float acc[4][4][4];
    #pragma unroll
    for (int i = 0; i < 4; i++)
        #pragma unroll
        for (int j = 0; j < 4; j++)
            #pragma unroll
            for (int q = 0; q < 4; q++) acc[i][j][q] = 0.f;

    const uint32_t sbase = smem_u32(smem);

    auto stage = [&](int buf, int k0) {
        uint32_t b0 = sbase + (uint32_t)buf * (BUFSH * 2);
        #pragma unroll
        for (int l = 0; l < 2; l++) {
            int idx = tid + l * 256;
            int r = idx >> 2, v = idx & 3;
            uint32_t d = b0 + (uint32_t)(r * SSTR + v * 8) * 2;
            int row = row0 + r;
            int sz = (row < N) ? 16 : 0;
            size_t ga = (size_t)row * DH + k0 + v * 8;
            cp16(d,             &g_ah[ga], sz);
            cp16(d + 5120 * 2,  &g_al[ga], sz);
            size_t gb = (size_t)woff + (size_t)(col0 + r) * DH + k0 + v * 8;
            cp16(d + 10240 * 2, &g_wth[gb], 16);
            cp16(d + 15360 * 2, &g_wtl[gb], 16);
        }
        asm volatile("cp.async.commit_group;");
    };

    stage(0, 0);

    for (int c = 0; c < 8; c++) {
        int buf = c & 1;
        if (c < 7) {
            stage(buf ^ 1, (c + 1) * 32);
            asm volatile("cp.async.wait_group 1;");
        } else {
            asm volatile("cp.async.wait_group 0;");
        }
        __syncthreads();

        uint32_t bAh = sbase + (uint32_t)buf * (BUFSH * 2);
        uint32_t bAl = bAh + 5120 * 2;
        uint32_t bBh = bAh + 10240 * 2;
        uint32_t bBl = bAh + 15360 * 2;

        #pragma unroll
        for (int kk = 0; kk < 32; kk += 16) {
            uint32_t ah[4][4], al[4][4];
            #pragma unroll
            for (int tm = 0; tm < 4; tm++) {
                int r = wm * 64 + tm * 16 + (lane & 15);
                uint32_t off = (uint32_t)(r * SSTR + kk + (lane >> 4) * 8) * 2;
                ldsm_x4(ah[tm][0], ah[tm][1], ah[tm][2], ah[tm][3], bAh + off);
                ldsm_x4(al[tm][0], al[tm][1], al[tm][2], al[tm][3], bAl + off);
            }
            #pragma unroll
            for (int tn = 0; tn < 4; tn++) {
                int r = wn * 32 + tn * 8 + (lane & 7);
                uint32_t off = (uint32_t)(r * SSTR + kk + ((lane >> 3) & 1) * 8) * 2;
                uint32_t bh[2], bl[2];
                ldsm_x2(bh[0], bh[1], bBh + off);
                ldsm_x2(bl[0], bl[1], bBl + off);
                #pragma unroll
                for (int tm = 0; tm < 4; tm++) {
                    mma16816(acc[tm][tn], ah[tm], bh);
                    mma16816(acc[tm][tn], al[tm], bh);
                    mma16816(acc[tm][tn], ah[tm], bl);
                }
            }
        }
        __syncthreads();
    }

    // epilogue: fp32 acc -> fp16 g_h (half2 stores)
    #pragma unroll
    for (int tm = 0; tm < 4; tm++) {
        int r0r = row0 + wm * 64 + tm * 16 + (lane >> 2);
        #pragma unroll
        for (int tn = 0; tn < 4; tn++) {
            int col = col0 + wn * 32 + tn * 8 + (lane & 3) * 2;
            if (r0r < N)
                *(__half2*)&g_h[(size_t)r0r * M + col] =
                    __floats2half2_rn(acc[tm][tn][0], acc[tm][tn][1]);
            if (r0r + 8 < N)
                *(__half2*)&g_h[(size_t)(r0r + 8) * M + col] =
                    __floats2half2_rn(acc[tm][tn][2], acc[tm][tn][3]);
        }
    }
}

// ---------------- aggregation (fp16 gather) + fused relu/split ---------------
__device__ __forceinline__ void h8f(uint4 v, float* f) {
    const __half2* p = reinterpret_cast<const __half2*>(&v);
    #pragma unroll
    for (int i = 0; i < 4; i++) {
        float2 t = __half22float2(p[i]);
        f[2 * i] = t.x; f[2 * i + 1] = t.y;
    }
}

// 128 threads/block; each thread owns 8 fp16 columns (one 16B load per row).
// M=256: 32 thr/node, 4 nodes/block.  M=128: 16 thr/node, 8 nodes/block.
__global__ __launch_bounds__(128) void k_agg(const float* __restrict__ bias,
                                             float* __restrict__ oext,
                                             int M, int mode)
{
    const int tpn  = M >> 3;
    const int node = blockIdx.x * (128 / tpn) + threadIdx.x / tpn;
    const int c    = threadIdx.x % tpn;
    const int rstr = M >> 3;                    // uint4 per fp16 row

    const uint4* hb = (const uint4*)g_h;

    float di = g_dinv[node];
    float s  = di * di;
    float acc[8], tmp[8];
    h8f(hb[(size_t)node * rstr + c], tmp);
    float4 bv0 = *(const float4*)&bias[c * 8];
    float4 bv1 = *(const float4*)&bias[c * 8 + 4];
    acc[0] = fmaf(tmp[0], s, bv0.x); acc[1] = fmaf(tmp[1], s, bv0.y);
    acc[2] = fmaf(tmp[2], s, bv0.z); acc[3] = fmaf(tmp[3], s, bv0.w);
    acc[4] = fmaf(tmp[4], s, bv1.x); acc[5] = fmaf(tmp[5], s, bv1.y);
    acc[6] = fmaf(tmp[6], s, bv1.z); acc[7] = fmaf(tmp[7], s, bv1.w);

    int e   = g_rowptr[node];
    int end = g_rowptr[node + 1];

    for (; e + 3 < end; e += 4) {
        int   s0 = g_csr_src[e],     s1 = g_csr_src[e + 1];
        int   s2 = g_csr_src[e + 2], s3 = g_csr_src[e + 3];
        float w0 = g_csr_w[e],     w1 = g_csr_w[e + 1];
        float w2 = g_csr_w[e + 2], w3 = g_csr_w[e + 3];
        uint4 v0 = hb[(size_t)s0 * rstr + c];
        uint4 v1 = hb[(size_t)s1 * rstr + c];
        uint4 v2 = hb[(size_t)s2 * rstr + c];
        uint4 v3 = hb[(size_t)s3 * rstr + c];
        h8f(v0, tmp);
        #pragma unroll
        for (int j = 0; j < 8; j++) acc[j] = fmaf(tmp[j], w0, acc[j]);
        h8f(v1, tmp);
        #pragma unroll
        for (int j = 0; j < 8; j++) acc[j] = fmaf(tmp[j], w1, acc[j]);
        h8f(v2, tmp);
        #pragma unroll
        for (int j = 0; j < 8; j++) acc[j] = fmaf(tmp[j], w2, acc[j]);
        h8f(v3, tmp);
        #pragma unroll
        for (int j = 0; j < 8; j++) acc[j] = fmaf(tmp[j], w3, acc[j]);
    }
    for (; e < end; e++) {
        int   s0 = g_csr_src[e];
        float w0 = g_csr_w[e];
        h8f(hb[(size_t)s0 * rstr + c], tmp);
        #pragma unroll
        for (int j = 0; j < 8; j++) acc[j] = fmaf(tmp[j], w0, acc[j]);
    }

    if (mode == 0) {
        ushort4 hs0, hs1, ls0, ls1;
        #pragma unroll
        for (int j = 0; j < 8; j++) acc[j] = fmaxf(acc[j], 0.f);
        split1(acc[0], hs0.x, ls0.x); split1(acc[1], hs0.y, ls0.y);
        split1(acc[2], hs0.z, ls0.z); split1(acc[3], hs0.w, ls0.w);
        split1(acc[4], hs1.x, ls1.x); split1(acc[5], hs1.y, ls1.y);
        split1(acc[6], hs1.z, ls1.z); split1(acc[7], hs1.w, ls1.w);
        size_t o = (size_t)node * M + c * 8;
        *(ushort4*)&g_ah[o]     = hs0;
        *(ushort4*)&g_ah[o + 4] = hs1;
        *(ushort4*)&g_al[o]     = ls0;
        *(ushort4*)&g_al[o + 4] = ls1;
    } else {
        size_t o = (size_t)node * M + c * 8;
        *(float4*)&oext[o]     = make_float4(acc[0], acc[1], acc[2], acc[3]);
        *(float4*)&oext[o + 4] = make_float4(acc[4], acc[5], acc[6], acc[7]);
    }
}

// ---------------- launch -----------------------------------------------------
extern "C" void kernel_launch(void* const* d_in, const int* in_sizes, int n_in,
                              void* d_out, int out_size)
{
    const float* x  = (const float*)d_in[0];
    const void*  ei = d_in[1];
    const float* W1 = (const float*)d_in[2];
    const float* b1 = (const float*)d_in[3];
    const float* W2 = (const float*)d_in[4];
    const float* b2 = (const float*)d_in[5];
    const float* W3 = (const float*)d_in[6];
    const float* b3 = (const float*)d_in[7];
    float* out = (float*)d_out;

    const int N = NN;
    const int E = in_sizes[1] / 2;
    const int n4 = N * (DH / 4);
    const int SM_BYTES = 2 * BUFSH * 2;   // 81920

    cudaFuncSetAttribute(k_mgemm, cudaFuncAttributeMaxDynamicSharedMemorySize,
                         SM_BYTES);

    dim3 tg_h((N + 127) / 128, DH / 128);    // 391 x 2
    dim3 tg_o((N + 127) / 128, DOUT / 128);  // 391 x 1

    k_prep0<<<(n4 + 255) / 256, 256>>>(W1, W2, W3, x, ei, n4, E);   // 0
    k_scan <<<1, 1024>>>();                                         // 1
    k_fill <<<(E + 255) / 256, 256>>>(ei, E);                       // 2

    k_mgemm<<<tg_h, 256, SM_BYTES>>>(N, DH, 0);                     // 3
    k_agg  <<<NN / 4, 128>>>(b1, out, DH, 0);                       // 4

    k_mgemm<<<tg_h, 256, SM_BYTES>>>(N, DH, 65536);                 // 5
    k_agg  <<<NN / 4, 128>>>(b2, out, DH, 0);                       // 6

    k_mgemm<<<tg_o, 256, SM_BYTES>>>(N, DOUT, 131072);              // 7
    k_agg  <<<NN / 8, 128>>>(b3, out, DOUT, 1);                     // 8
}

// round 12
// speedup vs baseline: 1.0592x; 1.0152x over previous
#include <cuda_runtime.h>
#include <cuda_bf16.h>
#include <cuda_fp16.h>
#include <math.h>
#include <stdint.h>

#define NN    50000
#define DH    256
#define DOUT  128
#define EMAX  800000

// ---------------- scratch (device globals; referenced by symbol only) --------
__device__ __half g_h  [(size_t)NN * DH];        // GEMM output (fp16)
__device__ __nv_bfloat16 g_ah[(size_t)NN * DH];  // A split hi (GEMM input)
__device__ __nv_bfloat16 g_al[(size_t)NN * DH];  // A split lo
__device__ __nv_bfloat16 g_wth[2 * 65536 + 32768]; // W^T hi (3 layers, [m][k])
__device__ __nv_bfloat16 g_wtl[2 * 65536 + 32768]; // W^T lo
__device__ float g_dinv[NN];
__device__ int   g_cnt [NN];                     // zero-init; re-zeroed by k_scan
__device__ int   g_rowptr[NN + 1];
__device__ int   g_cursor[NN];
__device__ int2  g_csr [EMAX];                   // {src, w as int bits}
__device__ int   g_is64;

__device__ __forceinline__ uint32_t smem_u32(const void* p) {
    uint32_t a;
    asm("{ .reg .u64 t; cvta.to.shared.u64 t, %1; cvt.u32.u64 %0, t; }"
        : "=r"(a) : "l"(p));
    return a;
}

// ---------------- hi/lo split --------------------------------------------------
__device__ __forceinline__ void split1(float v, unsigned short& hb, unsigned short& lb) {
    __nv_bfloat16 h = __float2bfloat16(v);
    float hf = __bfloat162float(h);
    __nv_bfloat16 l = __float2bfloat16(v - hf);
    hb = reinterpret_cast<unsigned short&>(h);
    lb = reinterpret_cast<unsigned short&>(l);
}

__device__ __forceinline__ int clampi(int v) { return min(max(v, 0), NN - 1); }

// ---------------- fused edge-independent prep ---------------------------------
__global__ void k_prep0(const float* __restrict__ W1,
                        const float* __restrict__ W2,
                        const float* __restrict__ W3,
                        const float* __restrict__ x,
                        const void* __restrict__ ei, int n4, int E) {
    int i = blockIdx.x * blockDim.x + threadIdx.x;

    // per-block dtype probe (int64 node ids < 50000 -> odd int32 words all 0)
    __shared__ int s_any;
    if (threadIdx.x == 0) s_any = 0;
    __syncthreads();
    {
        const int* ei32 = (const int*)ei;
        int a = 0;
        for (int k = threadIdx.x; k < 1024; k += blockDim.x)
            if (ei32[2 * k + 1] != 0) a = 1;
        if (a) atomicOr(&s_any, 1);
    }
    __syncthreads();
    const int is64 = s_any ? 0 : 1;
    if (i == 0) g_is64 = is64;

    // x split: fp32 -> hi/lo bf16
    if (i < n4) {
        float4 v = ((const float4*)x)[i];
        ushort4 hv, lv;
        split1(v.x, hv.x, lv.x);
        split1(v.y, hv.y, lv.y);
        split1(v.z, hv.z, lv.z);
        split1(v.w, hv.w, lv.w);
        ((ushort4*)g_ah)[i] = hv;
        ((ushort4*)g_al)[i] = lv;
    }
    // weights
    if (i < 163840) {
        const float* W; int M, off, j = i;
        if (j < 65536)       { W = W1; M = DH;   off = 0;      }
        else if (j < 131072) { W = W2; M = DH;   off = 65536;  j -= 65536;  }
        else                 { W = W3; M = DOUT; off = 131072; j -= 131072; }
        int k = j / M, m = j % M;
        unsigned short hb, lb;
        split1(W[j], hb, lb);
        g_wth[off + (size_t)m * DH + k] = reinterpret_cast<__nv_bfloat16&>(hb);
        g_wtl[off + (size_t)m * DH + k] = reinterpret_cast<__nv_bfloat16&>(lb);
    }
    // degree count
    if (i < E) {
        int d;
        if (is64) d = (int)((const long long*)ei)[(size_t)E + i];
        else      d = ((const int*)ei)[(size_t)E + i];
        atomicAdd(&g_cnt[clampi(d)], 1);
    }
}

__device__ __forceinline__ int ld_idx(const void* ei, size_t pos) {
    int v;
    if (g_is64) v = (int)((const long long*)ei)[pos];
    else        v = ((const int*)ei)[pos];
    return clampi(v);
}

// exclusive scan over g_cnt + dinv + re-zero cnt for next replay
__global__ void k_scan() {
    const int T = 1024;
    __shared__ int part[T];
    int tid = threadIdx.x;
    int chunk = (NN + T - 1) / T;
    int base = tid * chunk;
    int sum = 0;
    for (int i = 0; i < chunk; i++) {
        int j = base + i;
        if (j < NN) {
            int c = g_cnt[j];
            sum += c;
            g_dinv[j] = rsqrtf(1.0f + (float)c);
        }
    }
    part[tid] = sum;
    __syncthreads();
    for (int off = 1; off < T; off <<= 1) {
        int v = (tid >= off) ? part[tid - off] : 0;
        __syncthreads();
        part[tid] += v;
        __syncthreads();
    }
    int run = (tid > 0) ? part[tid - 1] : 0;
    for (int i = 0; i < chunk; i++) {
        int j = base + i;
        if (j < NN) {
            int c = g_cnt[j];
            g_rowptr[j] = run;
            g_cursor[j] = run;
            g_cnt[j]    = 0;
            run += c;
        }
    }
    if (tid == T - 1) g_rowptr[NN] = run;
}

// CSR fill: packed {src, norm}
__global__ void k_fill(const void* __restrict__ ei, int E) {
    int e = blockIdx.x * blockDim.x + threadIdx.x;
    if (e < E) {
        int s = ld_idx(ei, (size_t)e);
        int d = ld_idx(ei, (size_t)E + e);
        int pos = atomicAdd(&g_cursor[d], 1);
        g_csr[pos] = make_int2(s, __float_as_int(g_dinv[s] * g_dinv[d]));
    }
}

// ---------------- mma.sync bf16 split GEMM with cp.async double buffer ---------
#define SSTR 40
#define BUFSH 20480

__device__ __forceinline__ void ldsm_x4(uint32_t& r0, uint32_t& r1,
                                        uint32_t& r2, uint32_t& r3, uint32_t a) {
    asm volatile("ldmatrix.sync.aligned.m8n8.x4.shared.b16 {%0,%1,%2,%3}, [%4];"
                 : "=r"(r0), "=r"(r1), "=r"(r2), "=r"(r3) : "r"(a));
}
__device__ __forceinline__ void mma16816(float* d, const uint32_t* a, const uint32_t* b) {
    asm volatile(
        "mma.sync.aligned.m16n8k16.row.col.f32.bf16.bf16.f32 "
        "{%0,%1,%2,%3}, {%4,%5,%6,%7}, {%8,%9}, {%0,%1,%2,%3};"
        : "+f"(d[0]), "+f"(d[1]), "+f"(d[2]), "+f"(d[3])
        : "r"(a[0]), "r"(a[1]), "r"(a[2]), "r"(a[3]), "r"(b[0]), "r"(b[1]));
}
__device__ __forceinline__ void cp16(uint32_t d, const void* s, int sz) {
    asm volatile("cp.async.cg.shared.global [%0], [%1], 16, %2;"
                 :: "r"(d), "l"(s), "r"(sz));
}

__global__ __launch_bounds__(256) void k_mgemm(int N, int M, int woff) {
    extern __shared__ __align__(16) unsigned short smem[];

    const int tid = threadIdx.x;
    const int wid = tid >> 5;
    const int lane = tid & 31;
    const int wm = wid >> 2;
    const int wn = wid & 3;
    const int row0 = blockIdx.x * 128;
    const int col0 = blockIdx.y * 128;

    float acc[4][4][4];
    #pragma unroll
    for (int i = 0; i < 4; i++)
        #pragma unroll
        for (int j = 0; j < 4; j++)
            #pragma unroll
            for (int q = 0; q < 4; q++) acc[i][j][q] = 0.f;

    const uint32_t sbase = smem_u32(smem);

    auto stage = [&](int buf, int k0) {
        uint32_t b0 = sbase + (uint32_t)buf * (BUFSH * 2);
        #pragma unroll
        for (int l = 0; l < 2; l++) {
            int idx = tid + l * 256;
            int r = idx >> 2, v = idx & 3;
            uint32_t d = b0 + (uint32_t)(r * SSTR + v * 8) * 2;
            int row = row0 + r;
            int sz = (row < N) ? 16 : 0;
            size_t ga = (size_t)row * DH + k0 + v * 8;
            cp16(d,             &g_ah[ga], sz);
            cp16(d + 5120 * 2,  &g_al[ga], sz);
            size_t gb = (size_t)woff + (size_t)(col0 + r) * DH + k0 + v * 8;
            cp16(d + 10240 * 2, &g_wth[gb], 16);
            cp16(d + 15360 * 2, &g_wtl[gb], 16);
        }
        asm volatile("cp.async.commit_group;");
    };

    stage(0, 0);

    for (int c = 0; c < 8; c++) {
        int buf = c & 1;
        if (c < 7) {
            stage(buf ^ 1, (c + 1) * 32);
            asm volatile("cp.async.wait_group 1;");
        } else {
            asm volatile("cp.async.wait_group 0;");
        }
        __syncthreads();

        uint32_t bAh = sbase + (uint32_t)buf * (BUFSH * 2);
        uint32_t bAl = bAh + 5120 * 2;
        uint32_t bBh = bAh + 10240 * 2;
        uint32_t bBl = bAh + 15360 * 2;

        #pragma unroll
        for (int kk = 0; kk < 32; kk += 16) {
            uint32_t ah[4][4], al[4][4];
            #pragma unroll
            for (int tm = 0; tm < 4; tm++) {
                int r = wm * 64 + tm * 16 + (lane & 15);
                uint32_t off = (uint32_t)(r * SSTR + kk + (lane >> 4) * 8) * 2;
                ldsm_x4(ah[tm][0], ah[tm][1], ah[tm][2], ah[tm][3], bAh + off);
                ldsm_x4(al[tm][0], al[tm][1], al[tm][2], al[tm][3], bAl + off);
            }
            // B: one x4 covers two n-tiles (lanes 16-31 -> rows +8)
            #pragma unroll
            for (int tn = 0; tn < 4; tn += 2) {
                int r = wn * 32 + tn * 8 + (lane & 7) + ((lane >> 4) << 3);
                uint32_t off = (uint32_t)(r * SSTR + kk + ((lane >> 3) & 1) * 8) * 2;
                uint32_t bh[4], bl[4];
                ldsm_x4(bh[0], bh[1], bh[2], bh[3], bBh + off);
                ldsm_x4(bl[0], bl[1], bl[2], bl[3], bBl + off);
                #pragma unroll
                for (int tm = 0; tm < 4; tm++) {
                    mma16816(acc[tm][tn],     ah[tm], bh);
                    mma16816(acc[tm][tn],     al[tm], bh);
                    mma16816(acc[tm][tn],     ah[tm], bl);
                    mma16816(acc[tm][tn + 1], ah[tm], bh + 2);
                    mma16816(acc[tm][tn + 1], al[tm], bh + 2);
                    mma16816(acc[tm][tn + 1], ah[tm], bl + 2);
                }
            }
        }
        __syncthreads();
    }

    // epilogue: fp32 acc -> fp16 g_h
    #pragma unroll
    for (int tm = 0; tm < 4; tm++) {
        int r0r = row0 + wm * 64 + tm * 16 + (lane >> 2);
        #pragma unroll
        for (int tn = 0; tn < 4; tn++) {
            int col = col0 + wn * 32 + tn * 8 + (lane & 3) * 2;
            if (r0r < N)
                *(__half2*)&g_h[(size_t)r0r * M + col] =
                    __floats2half2_rn(acc[tm][tn][0], acc[tm][tn][1]);
            if (r0r + 8 < N)
                *(__half2*)&g_h[(size_t)(r0r + 8) * M + col] =
                    __floats2half2_rn(acc[tm][tn][2], acc[tm][tn][3]);
        }
    }
}

// ---------------- aggregation (fp16 gather, MLP 8) + fused relu/split --------
__device__ __forceinline__ void h8f(uint4 v, float* f) {
    const __half2* p = reinterpret_cast<const __half2*>(&v);
    #pragma unroll
    for (int i = 0; i < 4; i++) {
        float2 t = __half22float2(p[i]);
        f[2 * i] = t.x; f[2 * i + 1] = t.y;
    }
}

__global__ __launch_bounds__(128) void k_agg(const float* __restrict__ bias,
                                             float* __restrict__ oext,
                                             int M, int mode)
{
    const int tpn  = M >> 3;
    const int node = blockIdx.x * (128 / tpn) + threadIdx.x / tpn;
    const int c    = threadIdx.x % tpn;
    const int rstr = M >> 3;

    const uint4* hb = (const uint4*)g_h;

    float di = g_dinv[node];
    float s  = di * di;
    float acc[8], tmp[8];
    h8f(hb[(size_t)node * rstr + c], tmp);
    float4 bv0 = *(const float4*)&bias[c * 8];
    float4 bv1 = *(const float4*)&bias[c * 8 + 4];
    acc[0] = fmaf(tmp[0], s, bv0.x); acc[1] = fmaf(tmp[1], s, bv0.y);
    acc[2] = fmaf(tmp[2], s, bv0.z); acc[3] = fmaf(tmp[3], s, bv0.w);
    acc[4] = fmaf(tmp[4], s, bv1.x); acc[5] = fmaf(tmp[5], s, bv1.y);
    acc[6] = fmaf(tmp[6], s, bv1.z); acc[7] = fmaf(tmp[7], s, bv1.w);

    int e   = g_rowptr[node];
    int end = g_rowptr[node + 1];

    // unroll 8: 8 independent 16B gathers in flight
    for (; e + 7 < end; e += 8) {
        int2 p[8];
        #pragma unroll
        for (int j = 0; j < 8; j++) p[j] = g_csr[e + j];
        uint4 v[8];
        #pragma unroll
        for (int j = 0; j < 8; j++) v[j] = hb[(size_t)p[j].x * rstr + c];
        #pragma unroll
        for (int j = 0; j < 8; j++) {
            float w = __int_as_float(p[j].y);
            h8f(v[j], tmp);
            #pragma unroll
            for (int q = 0; q < 8; q++) acc[q] = fmaf(tmp[q], w, acc[q]);
        }
    }
    for (; e + 3 < end; e += 4) {
        int2 p[4];
        #pragma unroll
        for (int j = 0; j < 4; j++) p[j] = g_csr[e + j];
        uint4 v[4];
        #pragma unroll
        for (int j = 0; j < 4; j++) v[j] = hb[(size_t)p[j].x * rstr + c];
        #pragma unroll
        for (int j = 0; j < 4; j++) {
            float w = __int_as_float(p[j].y);
            h8f(v[j], tmp);
            #pragma unroll
            for (int q = 0; q < 8; q++) acc[q] = fmaf(tmp[q], w, acc[q]);
        }
    }
    for (; e < end; e++) {
        int2 p = g_csr[e];
        float w = __int_as_float(p.y);
        h8f(hb[(size_t)p.x * rstr + c], tmp);
        #pragma unroll
        for (int q = 0; q < 8; q++) acc[q] = fmaf(tmp[q], w, acc[q]);
    }

    if (mode == 0) {
        ushort4 hs0, hs1, ls0, ls1;
        #pragma unroll
        for (int j = 0; j < 8; j++) acc[j] = fmaxf(acc[j], 0.f);
        split1(acc[0], hs0.x, ls0.x); split1(acc[1], hs0.y, ls0.y);
        split1(acc[2], hs0.z, ls0.z); split1(acc[3], hs0.w, ls0.w);
        split1(acc[4], hs1.x, ls1.x); split1(acc[5], hs1.y, ls1.y);
        split1(acc[6], hs1.z, ls1.z); split1(acc[7], hs1.w, ls1.w);
        size_t o = (size_t)node * M + c * 8;
        *(ushort4*)&g_ah[o]     = hs0;
        *(ushort4*)&g_ah[o + 4] = hs1;
        *(ushort4*)&g_al[o]     = ls0;
        *(ushort4*)&g_al[o + 4] = ls1;
    } else {
        size_t o = (size_t)node * M + c * 8;
        *(float4*)&oext[o]     = make_float4(acc[0], acc[1], acc[2], acc[3]);
        *(float4*)&oext[o + 4] = make_float4(acc[4], acc[5], acc[6], acc[7]);
    }
}

// ---------------- launch -----------------------------------------------------
extern "C" void kernel_launch(void* const* d_in, const int* in_sizes, int n_in,
                              void* d_out, int out_size)
{
    const float* x  = (const float*)d_in[0];
    const void*  ei = d_in[1];
    const float* W1 = (const float*)d_in[2];
    const float* b1 = (const float*)d_in[3];
    const float* W2 = (const float*)d_in[4];
    const float* b2 = (const float*)d_in[5];
    const float* W3 = (const float*)d_in[6];
    const float* b3 = (const float*)d_in[7];
    float* out = (float*)d_out;

    const int N = NN;
    const int E = in_sizes[1] / 2;
    const int n4 = N * (DH / 4);
    const int SM_BYTES = 2 * BUFSH * 2;   // 81920

    cudaFuncSetAttribute(k_mgemm, cudaFuncAttributeMaxDynamicSharedMemorySize,
                         SM_BYTES);

    dim3 tg_h((N + 127) / 128, DH / 128);    // 391 x 2
    dim3 tg_o((N + 127) / 128, DOUT / 128);  // 391 x 1

    k_prep0<<<(n4 + 255) / 256, 256>>>(W1, W2, W3, x, ei, n4, E);   // 0
    k_scan <<<1, 1024>>>();                                         // 1
    k_fill <<<(E + 255) / 256, 256>>>(ei, E);                       // 2

    k_mgemm<<<tg_h, 256, SM_BYTES>>>(N, DH, 0);                     // 3
    k_agg  <<<NN / 4, 128>>>(b1, out, DH, 0);                       // 4

    k_mgemm<<<tg_h, 256, SM_BYTES>>>(N, DH, 65536);                 // 5
    k_agg  <<<NN / 4, 128>>>(b2, out, DH, 0);                       // 6

    k_mgemm<<<tg_o, 256, SM_BYTES>>>(N, DOUT, 131072);              // 7
    k_agg  <<<NN / 8, 128>>>(b3, out, DOUT, 1);                     // 8
}